// round 10
// baseline (speedup 1.0000x reference)
#include <cuda_runtime.h>
#include <cstdint>

// Shift op: x[32,64,56,56] -> out[32,576,56,56]
// out[n, c*9 + s, y, x] = x[n, c, y + s/3 - 1, x + s%3 - 1], zero-padded.
//
// R10: one block per (nc, s) output plane; blockIdx.x = nc*9 + s, so the
// grid's store stream is PERFECTLY SEQUENTIAL across all of global memory
// (each block writes exactly bytes [b*12544, (b+1)*12544)). (dy,dx) are
// uniform per block. Each output float4: 1 vec load + <=1 edge scalar
// (input is L2-resident; evict-last hint), .cs store.

#define N_  32
#define C_  64
#define H_  56
#define W_  56
#define W4 (W_ / 4)          // 14
#define PLANE_V4 (H_ * W4)   // 784 float4 per (nc,s) plane

__device__ __forceinline__ uint64_t mk_policy() {
    uint64_t p;
    asm("createpolicy.fractional.L2::evict_last.b64 %0, 1.0;" : "=l"(p));
    return p;
}
__device__ __forceinline__ float4 ldg_el4(const float* p, uint64_t pol) {
    float4 v;
    asm volatile("ld.global.nc.L2::cache_hint.v4.f32 {%0,%1,%2,%3}, [%4], %5;"
                 : "=f"(v.x), "=f"(v.y), "=f"(v.z), "=f"(v.w)
                 : "l"(p), "l"(pol));
    return v;
}
__device__ __forceinline__ float ldg_el1(const float* p, uint64_t pol) {
    float v;
    asm volatile("ld.global.nc.L2::cache_hint.f32 %0, [%1], %2;"
                 : "=f"(v) : "l"(p), "l"(pol));
    return v;
}

__global__ __launch_bounds__(256) void shift_kernel(
    const float* __restrict__ in, float* __restrict__ out)
{
    const uint64_t pol = mk_policy();

    const int b  = blockIdx.x;        // nc*9 + s
    const int s  = b % 9;
    const int nc = b / 9;
    const int dy = s / 3;             // uniform in block
    const int dx = s - dy * 3;        // uniform in block

    const float* plane = in + (long long)nc * (H_ * W_);
    float4* oplane = reinterpret_cast<float4*>(out) + (long long)b * PLANE_V4;

    // 784 output vectors, 256 threads -> 4 ragged iterations
    for (int v4 = threadIdx.x; v4 < PLANE_V4; v4 += blockDim.x) {
        int y  = v4 / W4;
        int x4 = v4 - y * W4;
        int x0 = x4 * 4;
        int sy = y + dy - 1;

        float4 o;
        if ((unsigned)sy >= (unsigned)H_) {
            o = make_float4(0.f, 0.f, 0.f, 0.f);
        } else {
            const float* row = plane + sy * W_;
            float4 vv = ldg_el4(row + x0, pol);
            if (dx == 1) {
                o = vv;
            } else if (dx == 0) {
                float l = (x0 > 0) ? ldg_el1(row + x0 - 1, pol) : 0.f;
                o = make_float4(l, vv.x, vv.y, vv.z);
            } else { // dx == 2
                float r = (x0 + 4 < W_) ? ldg_el1(row + x0 + 4, pol) : 0.f;
                o = make_float4(vv.y, vv.z, vv.w, r);
            }
        }
        __stcs(oplane + v4, o);
    }
}

extern "C" void kernel_launch(void* const* d_in, const int* in_sizes, int n_in,
                              void* d_out, int out_size) {
    const float* x = (const float*)d_in[0];
    float* out = (float*)d_out;
    int blocks = N_ * C_ * 9;   // 18432 blocks, one per (nc,s) plane
    shift_kernel<<<blocks, 256>>>(x, out);
}